// round 6
// baseline (speedup 1.0000x reference)
#include <cuda_runtime.h>
#include <cuda_fp16.h>
#include <cstdint>

#define CHAR_VOCAB 1001
#define EMB 256
#define H 192
#define G3 576   // 3*H
#define BATCH 32
#define SEQL 2048
#define NSPAN 512

// ---------------- scratch (no cudaMalloc allowed) ----------------
__device__ float g_proj[2][CHAR_VOCAB * G3];                 // 2 x 2.3 MB
__device__ float g_allh[(size_t)BATCH * SEQL * 2 * H];       // 100.7 MB

// ---------------- kernel 1: proj tables ----------------
// proj[d][v][g] = dot(emb[v], w_ih_d[g]) + b_ih_d[g]
#define VB 16
__global__ void proj_kernel(const float* __restrict__ emb,
                            const float* __restrict__ w_ih_f, const float* __restrict__ b_ih_f,
                            const float* __restrict__ w_ih_b, const float* __restrict__ b_ih_b) {
    __shared__ float embs[VB][EMB];
    const int dir = blockIdx.y;
    const float* __restrict__ w  = dir ? w_ih_b : w_ih_f;
    const float* __restrict__ bi = dir ? b_ih_b : b_ih_f;
    const int v0 = blockIdx.x * VB;

    for (int i = threadIdx.x; i < VB * EMB; i += blockDim.x) {
        int v = v0 + i / EMB;
        embs[i / EMB][i % EMB] = (v < CHAR_VOCAB) ? emb[(size_t)v * EMB + (i % EMB)] : 0.f;
    }
    __syncthreads();

    const int g = threadIdx.x;  // 0..575
    float acc[VB];
#pragma unroll
    for (int i = 0; i < VB; i++) acc[i] = 0.f;

    const float4* __restrict__ w4 = (const float4*)(w + (size_t)g * EMB);
    for (int e4 = 0; e4 < EMB / 4; e4++) {
        float4 wv = w4[e4];
#pragma unroll
        for (int i = 0; i < VB; i++) {
            float4 ev = *(const float4*)&embs[i][e4 * 4];
            acc[i] = fmaf(wv.x, ev.x, fmaf(wv.y, ev.y, fmaf(wv.z, ev.z, fmaf(wv.w, ev.w, acc[i]))));
        }
    }
    float bb = bi[g];
#pragma unroll
    for (int i = 0; i < VB; i++) {
        int v = v0 + i;
        if (v < CHAR_VOCAB) g_proj[dir][(size_t)v * G3 + g] = acc[i] + bb;
    }
}

// ---------------- kernel 2: GRU recurrence ----------------
// grid (2 dirs, 32 batch), 192 threads. W_hh fp16 in smem, everything else fp32.
// smem: W 221184 B + ids 8192 B + 2x h buffers 1536 B = 230912 B
#define SMEM_W_BYTES   (3 * 24 * H * 8 * 2)   // 221184
#define SMEM_IDS_OFF   SMEM_W_BYTES
#define SMEM_H_OFF     (SMEM_W_BYTES + SEQL * 4)
#define SMEM_TOTAL     (SMEM_H_OFF + 2 * H * 4)

__device__ __forceinline__ float sigf(float x) {
    return __fdividef(1.f, 1.f + __expf(-x));
}
__device__ __forceinline__ float tanhf_fast(float x) {
    // tanh(x) = 2*sigmoid(2x) - 1  (exp-based, ~1e-7 accuracy)
    return fmaf(2.f, sigf(2.f * x), -1.f);
}

__global__ void __launch_bounds__(192, 1)
gru_kernel(const int* __restrict__ char_ids,
           const float* __restrict__ w_hh_f, const float* __restrict__ b_hh_f,
           const float* __restrict__ w_hh_b, const float* __restrict__ b_hh_b) {
    extern __shared__ unsigned char smem[];
    __half* Ws   = (__half*)smem;                     // [3][24][192][8] halves
    int*    ids_s = (int*)(smem + SMEM_IDS_OFF);      // [2048]
    float*  hA   = (float*)(smem + SMEM_H_OFF);       // [192]
    float*  hB   = hA + H;                            // [192]

    const int dir = blockIdx.x;
    const int b   = blockIdx.y;
    const float* __restrict__ whh = dir ? w_hh_b : w_hh_f;
    const float* __restrict__ bhh = dir ? b_hh_b : b_hh_f;
    const float* __restrict__ proj = g_proj[dir];
    const int tid = threadIdx.x;

    // Stage W_hh into smem as fp16, layout [gate][k/8][row%192][k%8] so that
    // LDS.128 per lane is contiguous across the warp (conflict-free).
    for (int idx = tid; idx < G3 * H; idx += blockDim.x) {
        int row = idx / H, k = idx % H;
        int gg = row / H, j = row % H;
        Ws[((((size_t)gg * 24) + (k >> 3)) * H + j) * 8 + (k & 7)] = __float2half_rn(whh[idx]);
    }
    const int* __restrict__ myids = char_ids + (size_t)b * SEQL;
    for (int t = tid; t < SEQL; t += blockDim.x) ids_s[t] = myids[t];
    hA[tid] = 0.f;
    hB[tid] = 0.f;
    __syncthreads();

    const int j = tid;
    const float bhr = bhh[j], bhz = bhh[H + j], bhn = bhh[2 * H + j];
    float h_j = 0.f;
    float* allh_base = g_allh + ((size_t)b * SEQL) * (2 * H) + dir * H + j;

    // prefetch xp for step 0
    {
        int t0 = dir ? (SEQL - 1) : 0;
        int id0 = ids_s[t0];
        (void)id0;
    }
    int id0 = ids_s[dir ? (SEQL - 1) : 0];
    const float* p0 = proj + (size_t)id0 * G3 + j;
    float xr = p0[0], xz = p0[H], xn = p0[2 * H];

    const uint4* __restrict__ W4 = (const uint4*)Ws;  // [3*24][192] of 8-half vectors

#pragma unroll 1
    for (int s = 0; s < SEQL; s++) {
        // prefetch next step's xp (independent of h -> fully hidden)
        int sn = (s + 1 < SEQL) ? s + 1 : s;
        int tn = dir ? (SEQL - 1 - sn) : sn;
        int idn = ids_s[tn];
        const float* pn = proj + (size_t)idn * G3 + j;
        float xrN = pn[0], xzN = pn[H], xnN = pn[2 * H];

        const float* hb = (s & 1) ? hB : hA;
        float aR0 = bhr, aR1 = 0.f;
        float aZ0 = bhz, aZ1 = 0.f;
        float aN0 = bhn, aN1 = 0.f;

#pragma unroll
        for (int kg = 0; kg < 24; kg++) {
            float4 h0 = *(const float4*)(hb + kg * 8);
            float4 h1 = *(const float4*)(hb + kg * 8 + 4);
            uint4 wr = W4[(0 * 24 + kg) * H + j];
            uint4 wz = W4[(1 * 24 + kg) * H + j];
            uint4 wn = W4[(2 * 24 + kg) * H + j];
            {
                float2 f0 = __half22float2(*(__half2*)&wr.x);
                float2 f1 = __half22float2(*(__half2*)&wr.y);
                float2 f2 = __half22float2(*(__half2*)&wr.z);
                float2 f3 = __half22float2(*(__half2*)&wr.w);
                aR0 = fmaf(f0.x, h0.x, aR0); aR1 = fmaf(f0.y, h0.y, aR1);
                aR0 = fmaf(f1.x, h0.z, aR0); aR1 = fmaf(f1.y, h0.w, aR1);
                aR0 = fmaf(f2.x, h1.x, aR0); aR1 = fmaf(f2.y, h1.y, aR1);
                aR0 = fmaf(f3.x, h1.z, aR0); aR1 = fmaf(f3.y, h1.w, aR1);
            }
            {
                float2 f0 = __half22float2(*(__half2*)&wz.x);
                float2 f1 = __half22float2(*(__half2*)&wz.y);
                float2 f2 = __half22float2(*(__half2*)&wz.z);
                float2 f3 = __half22float2(*(__half2*)&wz.w);
                aZ0 = fmaf(f0.x, h0.x, aZ0); aZ1 = fmaf(f0.y, h0.y, aZ1);
                aZ0 = fmaf(f1.x, h0.z, aZ0); aZ1 = fmaf(f1.y, h0.w, aZ1);
                aZ0 = fmaf(f2.x, h1.x, aZ0); aZ1 = fmaf(f2.y, h1.y, aZ1);
                aZ0 = fmaf(f3.x, h1.z, aZ0); aZ1 = fmaf(f3.y, h1.w, aZ1);
            }
            {
                float2 f0 = __half22float2(*(__half2*)&wn.x);
                float2 f1 = __half22float2(*(__half2*)&wn.y);
                float2 f2 = __half22float2(*(__half2*)&wn.z);
                float2 f3 = __half22float2(*(__half2*)&wn.w);
                aN0 = fmaf(f0.x, h0.x, aN0); aN1 = fmaf(f0.y, h0.y, aN1);
                aN0 = fmaf(f1.x, h0.z, aN0); aN1 = fmaf(f1.y, h0.w, aN1);
                aN0 = fmaf(f2.x, h1.x, aN0); aN1 = fmaf(f2.y, h1.y, aN1);
                aN0 = fmaf(f3.x, h1.z, aN0); aN1 = fmaf(f3.y, h1.w, aN1);
            }
        }

        float r = sigf(xr + aR0 + aR1);
        float z = sigf(xz + aZ0 + aZ1);
        float n = tanhf_fast(fmaf(r, aN0 + aN1, xn));
        h_j = fmaf(z, h_j - n, n);   // (1-z)*n + z*h

        float* ho = (s & 1) ? hA : hB;
        ho[j] = h_j;
        int t = dir ? (SEQL - 1 - s) : s;
        allh_base[(size_t)t * (2 * H)] = h_j;

        xr = xrN; xz = xzN; xn = xnN;
        __syncthreads();
    }
}

// ---------------- kernel 3: gather ----------------
// out[b][s][0:384]   = all_h[b][start_ids[b][s]][:]
// out[b][s][384:768] = all_h[b][end_ids[b][s]][:]
__global__ void gather_kernel(const int* __restrict__ start_ids,
                              const int* __restrict__ end_ids,
                              float* __restrict__ out) {
    const int s = blockIdx.x, b = blockIdx.y;
    const int tid = threadIdx.x;  // 192 threads, 1 float4 each
    const int st = start_ids[(size_t)b * NSPAN + s];
    const int en = end_ids[(size_t)b * NSPAN + s];
    float4* orow = (float4*)(out + ((size_t)b * NSPAN + s) * 768);
    const float4* allh = (const float4*)g_allh;
    if (tid < 96) {
        orow[tid] = allh[((size_t)b * SEQL + st) * 96 + tid];
    } else {
        orow[tid] = allh[((size_t)b * SEQL + en) * 96 + (tid - 96)];
    }
}

// ---------------- launch ----------------
extern "C" void kernel_launch(void* const* d_in, const int* in_sizes, int n_in,
                              void* d_out, int out_size) {
    const int*   char_ids  = (const int*)d_in[0];
    const int*   start_ids = (const int*)d_in[1];
    const int*   end_ids   = (const int*)d_in[2];
    const float* emb       = (const float*)d_in[3];
    const float* w_ih_f    = (const float*)d_in[4];
    const float* w_hh_f    = (const float*)d_in[5];
    const float* b_ih_f    = (const float*)d_in[6];
    const float* b_hh_f    = (const float*)d_in[7];
    const float* w_ih_b    = (const float*)d_in[8];
    const float* w_hh_b    = (const float*)d_in[9];
    const float* b_ih_b    = (const float*)d_in[10];
    const float* b_hh_b    = (const float*)d_in[11];
    float* out = (float*)d_out;

    cudaFuncSetAttribute(gru_kernel, cudaFuncAttributeMaxDynamicSharedMemorySize, SMEM_TOTAL);

    // 1) projection tables: proj[d] = emb @ w_ih_d^T + b_ih_d  [1001, 576]
    proj_kernel<<<dim3((CHAR_VOCAB + VB - 1) / VB, 2), G3>>>(emb, w_ih_f, b_ih_f, w_ih_b, b_ih_b);

    // 2) bidirectional GRU recurrence: 64 independent (batch, direction) CTAs
    gru_kernel<<<dim3(2, BATCH), H, SMEM_TOTAL>>>(char_ids, w_hh_f, b_hh_f, w_hh_b, b_hh_b);

    // 3) gather start/end hidden states into output [32, 512, 768]
    gather_kernel<<<dim3(NSPAN, BATCH), 192>>>(start_ids, end_ids, out);
}

// round 7
// speedup vs baseline: 1.4913x; 1.4913x over previous
#include <cuda_runtime.h>
#include <cstdint>

#define CHAR_VOCAB 1001
#define EMB 256
#define H 192
#define G3 576   // 3*H
#define BATCH 32
#define SEQL 2048
#define NSPAN 512

// cluster split
#define JH 96            // outputs per CTA
#define KS 4             // K-split ways
#define KC 48            // K per slice
#define NTHR (JH * KS)   // 384 threads

// ---------------- scratch (no cudaMalloc allowed) ----------------
__device__ float g_proj[2][CHAR_VOCAB * G3];                 // 2 x 2.3 MB
__device__ float g_allh[(size_t)BATCH * SEQL * 2 * H];       // 100.7 MB

// ---------------- kernel 1: proj tables (unchanged, verified) ----------------
#define VB 16
__global__ void proj_kernel(const float* __restrict__ emb,
                            const float* __restrict__ w_ih_f, const float* __restrict__ b_ih_f,
                            const float* __restrict__ w_ih_b, const float* __restrict__ b_ih_b) {
    __shared__ float embs[VB][EMB];
    const int dir = blockIdx.y;
    const float* __restrict__ w  = dir ? w_ih_b : w_ih_f;
    const float* __restrict__ bi = dir ? b_ih_b : b_ih_f;
    const int v0 = blockIdx.x * VB;

    for (int i = threadIdx.x; i < VB * EMB; i += blockDim.x) {
        int v = v0 + i / EMB;
        embs[i / EMB][i % EMB] = (v < CHAR_VOCAB) ? emb[(size_t)v * EMB + (i % EMB)] : 0.f;
    }
    __syncthreads();

    const int g = threadIdx.x;  // 0..575
    float acc[VB];
#pragma unroll
    for (int i = 0; i < VB; i++) acc[i] = 0.f;

    const float4* __restrict__ w4 = (const float4*)(w + (size_t)g * EMB);
    for (int e4 = 0; e4 < EMB / 4; e4++) {
        float4 wv = w4[e4];
#pragma unroll
        for (int i = 0; i < VB; i++) {
            float4 ev = *(const float4*)&embs[i][e4 * 4];
            acc[i] = fmaf(wv.x, ev.x, fmaf(wv.y, ev.y, fmaf(wv.z, ev.z, fmaf(wv.w, ev.w, acc[i]))));
        }
    }
    float bb = bi[g];
#pragma unroll
    for (int i = 0; i < VB; i++) {
        int v = v0 + i;
        if (v < CHAR_VOCAB) g_proj[dir][(size_t)v * G3 + g] = acc[i] + bb;
    }
}

// ---------------- PTX helpers ----------------
__device__ __forceinline__ uint32_t smem_u32(const void* p) {
    uint32_t a;
    asm("{ .reg .u64 t; cvta.to.shared.u64 t, %1; cvt.u32.u64 %0, t; }" : "=r"(a) : "l"(p));
    return a;
}
__device__ __forceinline__ uint32_t mapa_u32(uint32_t laddr, uint32_t peer) {
    uint32_t r;
    asm("mapa.shared::cluster.u32 %0, %1, %2;" : "=r"(r) : "r"(laddr), "r"(peer));
    return r;
}
__device__ __forceinline__ void mbar_init(uint32_t a, uint32_t cnt) {
    asm volatile("mbarrier.init.shared.b64 [%0], %1;" :: "r"(a), "r"(cnt) : "memory");
}
__device__ __forceinline__ void mbar_arrive_local(uint32_t a) {
    asm volatile("mbarrier.arrive.release.cluster.shared::cta.b64 _, [%0];" :: "r"(a) : "memory");
}
__device__ __forceinline__ void mbar_arrive_remote(uint32_t ra) {
    asm volatile("mbarrier.arrive.release.cluster.shared::cluster.b64 _, [%0];" :: "r"(ra) : "memory");
}
__device__ __forceinline__ void st_remote_f32(uint32_t raddr, float v) {
    asm volatile("st.shared::cluster.b32 [%0], %1;" :: "r"(raddr), "r"(__float_as_uint(v)) : "memory");
}
__device__ __forceinline__ void mbar_wait_parity(uint32_t a, uint32_t parity) {
    uint32_t done;
    asm volatile("{\n\t.reg .pred p;\n\t"
        "mbarrier.try_wait.parity.acquire.cluster.shared::cta.b64 p, [%1], %2;\n\t"
        "selp.b32 %0, 1, 0, p;\n\t}"
        : "=r"(done) : "r"(a), "r"(parity) : "memory");
    while (!done) {
        asm volatile("{\n\t.reg .pred p;\n\t"
            "mbarrier.try_wait.parity.acquire.cluster.shared::cta.b64 p, [%1], %2, 0x989680;\n\t"
            "selp.b32 %0, 1, 0, p;\n\t}"
            : "=r"(done) : "r"(a), "r"(parity) : "memory");
    }
}
__device__ __forceinline__ void cluster_barrier() {
    asm volatile("barrier.cluster.arrive.aligned;" ::: "memory");
    asm volatile("barrier.cluster.wait.aligned;" ::: "memory");
}

__device__ __forceinline__ float sigf(float x) {
    return __fdividef(1.f, 1.f + __expf(-x));
}
__device__ __forceinline__ float tanhf_fast(float x) {
    return fmaf(2.f, sigf(2.f * x), -1.f);
}
__device__ __forceinline__ uint32_t bf16rn(float f) {
    uint32_t u = __float_as_uint(f);
    return (u + 0x7FFFu + ((u >> 16) & 1u)) >> 16;
}

// one dual-MAC on a packed bf16 pair
#define DOT2(a0, a1, w, hx, hy) { \
    float wl = __uint_as_float((w) << 16); \
    float wh = __uint_as_float((w) & 0xFFFF0000u); \
    a0 = fmaf(wl, (hx), a0); a1 = fmaf(wh, (hy), a1); }

// ---------------- kernel 2: clustered GRU recurrence ----------------
// cluster(2,1,1): rank r owns global j in [96r, 96r+96). W_hh slice lives in
// REGISTERS as packed bf16 (72 u32/thread). 384 threads = (ks 0..3) x (jl 0..95);
// warp = 32 consecutive jl at fixed ks -> h reads are pure broadcasts.
__global__ void __launch_bounds__(NTHR, 1) __cluster_dims__(2, 1, 1)
gru_kernel(const int* __restrict__ char_ids,
           const float* __restrict__ w_hh_f, const float* __restrict__ b_hh_f,
           const float* __restrict__ w_hh_b, const float* __restrict__ b_hh_b) {
    __shared__ float hbuf[2][H];        // double-buffered full h (both halves)
    __shared__ float part[9][JH];       // partials: [(ks-1)*3+gate][jl]
    __shared__ int   ids_s[SEQL];
    __shared__ unsigned long long mbar;

    const int rank = blockIdx.x;        // cluster rank 0/1
    const int dir  = blockIdx.y;
    const int b    = blockIdx.z;
    const float* __restrict__ whh = dir ? w_hh_b : w_hh_f;
    const float* __restrict__ bhh = dir ? b_hh_b : b_hh_f;
    const float* __restrict__ proj = g_proj[dir];

    const int tid = threadIdx.x;
    const int ks  = tid / JH;           // 0..3  (uniform per warp)
    const int jl  = tid % JH;           // 0..95
    const int jg  = rank * JH + jl;     // global output index 0..191

    // ---- prologue ----
    if (tid == 0) mbar_init(smem_u32(&mbar), 2 * JH);   // 96 local + 96 remote arrivals
    ((float*)hbuf)[tid] = 0.f;                           // zero both buffers (384 floats)
    {
        const int* __restrict__ myids = char_ids + (size_t)b * SEQL;
        for (int t = tid; t < SEQL; t += NTHR) ids_s[t] = myids[t];
    }

    // W_hh slice -> registers, packed bf16 pairs: wv[g][q] = (k=2q lo, k=2q+1 hi)
    uint32_t wv[3][24];
#pragma unroll
    for (int g = 0; g < 3; g++) {
        const float2* __restrict__ wr2 =
            (const float2*)(whh + ((size_t)(g * H + jg)) * H + ks * KC);
#pragma unroll
        for (int q = 0; q < 24; q++) {
            float2 f = wr2[q];
            wv[g][q] = bf16rn(f.x) | (bf16rn(f.y) << 16);
        }
    }
    __syncthreads();
    cluster_barrier();   // mbar + hbuf init visible cluster-wide before any arrivals

    const uint32_t mbar_a = smem_u32(&mbar);
    const uint32_t peer = rank ^ 1;
    const uint32_t r_mbar = mapa_u32(mbar_a, peer);
    const uint32_t r_h0 = mapa_u32(smem_u32(&hbuf[0][jg]), peer);
    const uint32_t r_h1 = mapa_u32(smem_u32(&hbuf[1][jg]), peer);

    // ks0-only state
    float bhr = 0.f, bhz = 0.f, bhn = 0.f, h_j = 0.f;
    float xr = 0.f, xz = 0.f, xn = 0.f;
    float* allh_base = g_allh + ((size_t)b * SEQL) * (2 * H) + dir * H + jg;
    if (ks == 0) {
        bhr = bhh[jg]; bhz = bhh[H + jg]; bhn = bhh[2 * H + jg];
        int t0 = dir ? (SEQL - 1) : 0;
        const float* p0 = proj + (size_t)ids_s[t0] * G3 + jg;
        xr = p0[0]; xz = p0[H]; xn = p0[2 * H];
    }

#pragma unroll 1
    for (int s = 0; s < SEQL; s++) {
        // prefetch next step's xp (ks0 warps only; latency hidden by the dot)
        float xrN = 0.f, xzN = 0.f, xnN = 0.f;
        if (ks == 0) {
            int sn = (s + 1 < SEQL) ? s + 1 : s;
            int tn = dir ? (SEQL - 1 - sn) : sn;
            const float* pn = proj + (size_t)ids_s[tn] * G3 + jg;
            xrN = __ldg(pn); xzN = __ldg(pn + H); xnN = __ldg(pn + 2 * H);
        }

        const float* hb = &hbuf[s & 1][ks * KC];
        float aR0 = 0.f, aR1 = 0.f, aZ0 = 0.f, aZ1 = 0.f, aN0 = 0.f, aN1 = 0.f;
#pragma unroll
        for (int q = 0; q < 12; q++) {
            float4 h4 = *(const float4*)(hb + 4 * q);
            DOT2(aR0, aR1, wv[0][2 * q],     h4.x, h4.y);
            DOT2(aR0, aR1, wv[0][2 * q + 1], h4.z, h4.w);
            DOT2(aZ0, aZ1, wv[1][2 * q],     h4.x, h4.y);
            DOT2(aZ0, aZ1, wv[1][2 * q + 1], h4.z, h4.w);
            DOT2(aN0, aN1, wv[2][2 * q],     h4.x, h4.y);
            DOT2(aN0, aN1, wv[2][2 * q + 1], h4.z, h4.w);
        }

        if (ks != 0) {
            part[(ks - 1) * 3 + 0][jl] = aR0 + aR1;
            part[(ks - 1) * 3 + 1][jl] = aZ0 + aZ1;
            part[(ks - 1) * 3 + 2][jl] = aN0 + aN1;
        }
        __syncthreads();   // partials visible; also gates mbar phase advance

        if (ks == 0) {
            float aR = aR0 + aR1 + part[0][jl] + part[3][jl] + part[6][jl];
            float aZ = aZ0 + aZ1 + part[1][jl] + part[4][jl] + part[7][jl];
            float aN = aN0 + aN1 + part[2][jl] + part[5][jl] + part[8][jl];
            float r = sigf(xr + bhr + aR);
            float z = sigf(xz + bhz + aZ);
            float n = tanhf_fast(fmaf(r, aN + bhn, xn));
            h_j = fmaf(z, h_j - n, n);   // (1-z)*n + z*h

            int nxt = (s + 1) & 1;
            hbuf[nxt][jg] = h_j;                         // local half
            st_remote_f32((s & 1) ? r_h0 : r_h1, h_j);   // peer's copy
            int t = dir ? (SEQL - 1 - s) : s;
            allh_base[(size_t)t * (2 * H)] = h_j;

            xr = xrN; xz = xzN; xn = xnN;
            mbar_arrive_local(mbar_a);
            mbar_arrive_remote(r_mbar);
        }
        mbar_wait_parity(mbar_a, (uint32_t)(s & 1));
    }

    cluster_barrier();   // no CTA exits while peer may still write into it
}

// ---------------- kernel 3: gather (unchanged, verified) ----------------
__global__ void gather_kernel(const int* __restrict__ start_ids,
                              const int* __restrict__ end_ids,
                              float* __restrict__ out) {
    const int s = blockIdx.x, b = blockIdx.y;
    const int tid = threadIdx.x;  // 192 threads, 1 float4 each
    const int st = start_ids[(size_t)b * NSPAN + s];
    const int en = end_ids[(size_t)b * NSPAN + s];
    float4* orow = (float4*)(out + ((size_t)b * NSPAN + s) * 768);
    const float4* allh = (const float4*)g_allh;
    if (tid < 96) {
        orow[tid] = allh[((size_t)b * SEQL + st) * 96 + tid];
    } else {
        orow[tid] = allh[((size_t)b * SEQL + en) * 96 + (tid - 96)];
    }
}

// ---------------- launch ----------------
extern "C" void kernel_launch(void* const* d_in, const int* in_sizes, int n_in,
                              void* d_out, int out_size) {
    const int*   char_ids  = (const int*)d_in[0];
    const int*   start_ids = (const int*)d_in[1];
    const int*   end_ids   = (const int*)d_in[2];
    const float* emb       = (const float*)d_in[3];
    const float* w_ih_f    = (const float*)d_in[4];
    const float* w_hh_f    = (const float*)d_in[5];
    const float* b_ih_f    = (const float*)d_in[6];
    const float* b_hh_f    = (const float*)d_in[7];
    const float* w_ih_b    = (const float*)d_in[8];
    const float* w_hh_b    = (const float*)d_in[9];
    const float* b_ih_b    = (const float*)d_in[10];
    const float* b_hh_b    = (const float*)d_in[11];
    float* out = (float*)d_out;

    // 1) projection tables: proj[d] = emb @ w_ih_d^T + b_ih_d  [1001, 576]
    proj_kernel<<<dim3((CHAR_VOCAB + VB - 1) / VB, 2), G3>>>(emb, w_ih_f, b_ih_f, w_ih_b, b_ih_b);

    // 2) clustered bidirectional GRU: 64 recurrences x 2-CTA clusters = 128 CTAs
    gru_kernel<<<dim3(2, 2, BATCH), NTHR>>>(char_ids, w_hh_f, b_hh_f, w_hh_b, b_hh_b);

    // 3) gather start/end hidden states into output [32, 512, 768]
    gather_kernel<<<dim3(NSPAN, BATCH), 192>>>(start_ids, end_ids, out);
}